// round 1
// baseline (speedup 1.0000x reference)
#include <cuda_runtime.h>
#include <math.h>

// Problem constants (fixed shapes from reference setup_inputs)
#define B    8
#define C    192
#define C2   384
#define NH   4
#define CH   48
#define H    128
#define WD   128
#define HW   16384
#define NCHUNK 16
#define CHUNK  1024

// ---------------- scratch (static __device__ arrays; no runtime allocs) ----
__device__ float g_t1 [B * C2 * HW];   // conv1x1(x, w_qkv)      [8,384,16384]
__device__ float g_kv [B * C2 * HW];   // dwconv of t1           [8,384,16384]
__device__ float g_t2 [B * C  * HW];   // conv1x1(y, w_query)    [8,192,16384]
__device__ float g_q  [B * C  * HW];   // dwconv of t2           [8,192,16384]
__device__ float g_att[B * C  * HW];   // attn @ v               [8,192,16384]
__device__ float g_pS [B * NH * NCHUNK * CH * CH]; // split-K Gram partials
__device__ float g_pnq[B * NH * NCHUNK * CH];      // split-K |q|^2 partials
__device__ float g_pnk[B * NH * NCHUNK * CH];      // split-K |k|^2 partials
__device__ float g_attn[B * NH * CH * CH];          // softmax(attn) [32,48,48]

// ---------------- f32x2 packed-FMA helpers (sm_103a) ------------------------
__device__ __forceinline__ unsigned long long pk2(float v) {
    unsigned long long r;
    asm("mov.b64 %0, {%1, %1};" : "=l"(r) : "f"(v));
    return r;
}
__device__ __forceinline__ void fma2(unsigned long long& d,
                                     unsigned long long a,
                                     unsigned long long b) {
    asm("fma.rn.f32x2 %0, %1, %2, %0;" : "+l"(d) : "l"(a), "l"(b));
}
__device__ __forceinline__ float2 up2(unsigned long long v) {
    float lo, hi;
    asm("mov.b64 {%0, %1}, %2;" : "=f"(lo), "=f"(hi) : "l"(v));
    return make_float2(lo, hi);
}

// ---------------- 1x1 conv as GEMM: out[b,m,n] = sum_k W[m,k] * in[b,k,n] ---
// Block tile: 64 (M) x 128 (N), K-chunk 16. 128 threads, per-thread 8m x 8n,
// N-pairs accumulated with fma.rn.f32x2 (2x fp32 FMA throughput).
__global__ __launch_bounds__(128) void conv1x1_kernel(
    const float* __restrict__ in, const float* __restrict__ w,
    float* __restrict__ out, int Cin, int Cout)
{
    const int n0  = blockIdx.x * 128;
    const int m0  = blockIdx.y * 64;
    const int b   = blockIdx.z;
    const int tid = threadIdx.x;
    const int tx  = tid & 15;   // -> n (8 cols = 4 pairs)
    const int ty  = tid >> 4;   // -> m (8 rows)

    __shared__ float sW[64][17];                  // [m][k], padded
    __shared__ __align__(16) float sX[16][128];   // [k][n]

    const float* inb = in + ((size_t)b * Cin) * HW + n0;

    unsigned long long acc[8][4];
#pragma unroll
    for (int i = 0; i < 8; i++)
#pragma unroll
        for (int j = 0; j < 4; j++) acc[i][j] = 0ULL;

    for (int k0 = 0; k0 < Cin; k0 += 16) {
#pragma unroll
        for (int e = 0; e < 8; e++) {
            int idx = tid + e * 128;       // 0..1023
            int kk = idx & 15, mm = idx >> 4;
            sW[mm][kk] = w[(size_t)(m0 + mm) * Cin + (k0 + kk)];
        }
#pragma unroll
        for (int e = 0; e < 4; e++) {
            int idx = tid + e * 128;       // 0..511 float4 units
            int kk = idx >> 5, nv = idx & 31;
            ((float4*)(&sX[kk][0]))[nv] =
                ((const float4*)(inb + (size_t)(k0 + kk) * HW))[nv];
        }
        __syncthreads();
#pragma unroll
        for (int kk = 0; kk < 16; kk++) {
            const ulonglong2* bp = (const ulonglong2*)(&sX[kk][0]);
            ulonglong2 u0 = bp[tx * 2];
            ulonglong2 u1 = bp[tx * 2 + 1];
#pragma unroll
            for (int i = 0; i < 8; i++) {
                unsigned long long a2 = pk2(sW[ty * 8 + i][kk]);
                fma2(acc[i][0], a2, u0.x);
                fma2(acc[i][1], a2, u0.y);
                fma2(acc[i][2], a2, u1.x);
                fma2(acc[i][3], a2, u1.y);
            }
        }
        __syncthreads();
    }

    float* ob = out + ((size_t)b * Cout + m0 + ty * 8) * HW + n0 + tx * 8;
#pragma unroll
    for (int i = 0; i < 8; i++) {
        float2 r0 = up2(acc[i][0]);
        float2 r1 = up2(acc[i][1]);
        float2 r2 = up2(acc[i][2]);
        float2 r3 = up2(acc[i][3]);
        float4* p = (float4*)(ob + (size_t)i * HW);
        p[0] = make_float4(r0.x, r0.y, r1.x, r1.y);
        p[1] = make_float4(r2.x, r2.y, r3.x, r3.y);
    }
}

// ---------------- depthwise 3x3, SAME padding (cross-correlation) -----------
// Block: one (b, c, 8-row strip), 128 threads (one per column).
__global__ __launch_bounds__(128) void dwconv3x3_kernel(
    const float* __restrict__ in, const float* __restrict__ w9,
    float* __restrict__ out, int Cc)
{
    const int y0 = blockIdx.x * 8;
    const int c  = blockIdx.y;
    const int b  = blockIdx.z;
    const int x  = threadIdx.x;

    __shared__ float s[10][130];
    const float* ip = in  + ((size_t)b * Cc + c) * HW;
    float*       op = out + ((size_t)b * Cc + c) * HW;

    float wr[9];
#pragma unroll
    for (int t = 0; t < 9; t++) wr[t] = w9[c * 9 + t];

#pragma unroll
    for (int r = 0; r < 10; r++) {
        int yy = y0 - 1 + r;
        s[r][x + 1] = (yy >= 0 && yy < H) ? ip[yy * WD + x] : 0.0f;
    }
    if (x == 0) {
#pragma unroll
        for (int r = 0; r < 10; r++) { s[r][0] = 0.0f; s[r][129] = 0.0f; }
    }
    __syncthreads();

#pragma unroll
    for (int ry = 0; ry < 8; ry++) {
        float a =
            s[ry + 0][x + 0] * wr[0] + s[ry + 0][x + 1] * wr[1] + s[ry + 0][x + 2] * wr[2] +
            s[ry + 1][x + 0] * wr[3] + s[ry + 1][x + 1] * wr[4] + s[ry + 1][x + 2] * wr[5] +
            s[ry + 2][x + 0] * wr[6] + s[ry + 2][x + 1] * wr[7] + s[ry + 2][x + 2] * wr[8];
        op[(y0 + ry) * WD + x] = a;
    }
}

// ---------------- split-K Gram: S[c,d] = sum_n q[c,n]*k[d,n], + norms -------
// grid (NCHUNK, NH, B), 256 threads (16x16), per-thread 3x3 of the 48x48 tile.
__global__ __launch_bounds__(256) void gram_kernel()
{
    const int ck = blockIdx.x, h = blockIdx.y, b = blockIdx.z;
    const int tid = threadIdx.x;
    const int tx = tid & 15, ty = tid >> 4;

    const float* qp = g_q  + ((size_t)b * C  + h * CH) * HW + ck * CHUNK;
    const float* kp = g_kv + ((size_t)b * C2 + h * CH) * HW + ck * CHUNK;

    __shared__ float sQ[32][49];
    __shared__ float sK[32][49];

    float acc[3][3];
#pragma unroll
    for (int i = 0; i < 3; i++)
#pragma unroll
        for (int j = 0; j < 3; j++) acc[i][j] = 0.0f;
    float sq[3] = {0.f, 0.f, 0.f}, sk2[3] = {0.f, 0.f, 0.f};

    for (int nb = 0; nb < CHUNK; nb += 32) {
#pragma unroll
        for (int e = 0; e < 6; e++) {
            int idx = tid + e * 256;           // 0..1535 = 48 x 32
            int cc = idx >> 5, nn = idx & 31;
            sQ[nn][cc] = qp[(size_t)cc * HW + nb + nn];
            sK[nn][cc] = kp[(size_t)cc * HW + nb + nn];
        }
        __syncthreads();
#pragma unroll
        for (int kk = 0; kk < 32; kk++) {
            float a0 = sQ[kk][ty * 3 + 0];
            float a1 = sQ[kk][ty * 3 + 1];
            float a2 = sQ[kk][ty * 3 + 2];
            float b0 = sK[kk][tx * 3 + 0];
            float b1 = sK[kk][tx * 3 + 1];
            float b2 = sK[kk][tx * 3 + 2];
            acc[0][0] += a0 * b0; acc[0][1] += a0 * b1; acc[0][2] += a0 * b2;
            acc[1][0] += a1 * b0; acc[1][1] += a1 * b1; acc[1][2] += a1 * b2;
            acc[2][0] += a2 * b0; acc[2][1] += a2 * b1; acc[2][2] += a2 * b2;
            if (tx == 0) { sq[0]  += a0 * a0; sq[1]  += a1 * a1; sq[2]  += a2 * a2; }
            if (ty == 0) { sk2[0] += b0 * b0; sk2[1] += b1 * b1; sk2[2] += b2 * b2; }
        }
        __syncthreads();
    }

    const int base = (b * NH + h) * NCHUNK + ck;
    float* ps = g_pS + (size_t)base * (CH * CH);
#pragma unroll
    for (int i = 0; i < 3; i++)
#pragma unroll
        for (int j = 0; j < 3; j++)
            ps[(ty * 3 + i) * CH + tx * 3 + j] = acc[i][j];
    if (tx == 0) {
#pragma unroll
        for (int i = 0; i < 3; i++) g_pnq[base * CH + ty * 3 + i] = sq[i];
    }
    if (ty == 0) {
#pragma unroll
        for (int j = 0; j < 3; j++) g_pnk[base * CH + tx * 3 + j] = sk2[j];
    }
}

// ---------------- reduce partials, l2-normalize, temperature, softmax -------
__global__ __launch_bounds__(256) void reduce_softmax_kernel(
    const float* __restrict__ temperature)
{
    const int bh = blockIdx.x;      // b*NH + h, 0..31
    const int h  = bh & (NH - 1);
    const int tid = threadIdx.x;

    __shared__ float sS[CH * CH];
    __shared__ float snq[CH], snk[CH];

    for (int idx = tid; idx < CH * CH; idx += 256) {
        float s = 0.0f;
        for (int ck = 0; ck < NCHUNK; ck++)
            s += g_pS[(size_t)(bh * NCHUNK + ck) * (CH * CH) + idx];
        sS[idx] = s;
    }
    if (tid < CH) {
        float s = 0.0f;
        for (int ck = 0; ck < NCHUNK; ck++)
            s += g_pnq[(bh * NCHUNK + ck) * CH + tid];
        snq[tid] = fmaxf(sqrtf(s), 1e-12f);
    } else if (tid >= 64 && tid < 64 + CH) {
        int d = tid - 64;
        float s = 0.0f;
        for (int ck = 0; ck < NCHUNK; ck++)
            s += g_pnk[(bh * NCHUNK + ck) * CH + d];
        snk[d] = fmaxf(sqrtf(s), 1e-12f);
    }
    __syncthreads();

    const float t = temperature[h];
    for (int idx = tid; idx < CH * CH; idx += 256) {
        int cc = idx / CH, d = idx - cc * CH;
        sS[idx] = sS[idx] * t / (snq[cc] * snk[d]);
    }
    __syncthreads();

    if (tid < CH) {
        const int cc = tid;
        float m = -1e30f;
        for (int d = 0; d < CH; d++) m = fmaxf(m, sS[cc * CH + d]);
        float sum = 0.0f;
        for (int d = 0; d < CH; d++) {
            float e = expf(sS[cc * CH + d] - m);
            sS[cc * CH + d] = e;
            sum += e;
        }
        float inv = 1.0f / sum;
        for (int d = 0; d < CH; d++)
            g_attn[(size_t)bh * (CH * CH) + cc * CH + d] = sS[cc * CH + d] * inv;
    }
}

// ---------------- out[c,n] = sum_d attn[c,d] * v[d,n] -----------------------
// grid (HW/128, NH, B), 256 threads (ty=8 x tx=32), per-thread 6c x 4n.
__global__ __launch_bounds__(256) void attnv_kernel()
{
    const int n0 = blockIdx.x * 128;
    const int h  = blockIdx.y, b = blockIdx.z;
    const int tid = threadIdx.x;
    const int tx = tid & 31, ty = tid >> 5;

    __shared__ float sA[CH][CH];
    __shared__ __align__(16) float sV[CH][128];

    const float* vp = g_kv + ((size_t)b * C2 + C + h * CH) * HW + n0;
    const float* ap = g_attn + (size_t)(b * NH + h) * (CH * CH);

    for (int idx = tid; idx < CH * CH; idx += 256)
        sA[idx / CH][idx % CH] = ap[idx];
#pragma unroll
    for (int e = 0; e < 6; e++) {
        int idx = tid + e * 256;             // 0..1535 float4 units (48 x 32)
        int d = idx >> 5, nv = idx & 31;
        ((float4*)(&sV[d][0]))[nv] = ((const float4*)(vp + (size_t)d * HW))[nv];
    }
    __syncthreads();

    float4 acc[6];
#pragma unroll
    for (int i = 0; i < 6; i++) acc[i] = make_float4(0.f, 0.f, 0.f, 0.f);

    for (int d = 0; d < CH; d++) {
        float4 vv = ((const float4*)(&sV[d][0]))[tx];
#pragma unroll
        for (int i = 0; i < 6; i++) {
            float a = sA[ty * 6 + i][d];
            acc[i].x += a * vv.x; acc[i].y += a * vv.y;
            acc[i].z += a * vv.z; acc[i].w += a * vv.w;
        }
    }

    float* op = g_att + ((size_t)b * C + h * CH + ty * 6) * HW + n0 + tx * 4;
#pragma unroll
    for (int i = 0; i < 6; i++)
        *((float4*)(op + (size_t)i * HW)) = acc[i];
}

// ---------------- launcher ---------------------------------------------------
extern "C" void kernel_launch(void* const* d_in, const int* in_sizes, int n_in,
                              void* d_out, int out_size)
{
    const float* x           = (const float*)d_in[0];
    const float* y           = (const float*)d_in[1];
    const float* w_qkv       = (const float*)d_in[2];
    const float* w_qkv_dw    = (const float*)d_in[3];
    const float* w_query     = (const float*)d_in[4];
    const float* w_query_dw  = (const float*)d_in[5];
    const float* w_proj      = (const float*)d_in[6];
    const float* temperature = (const float*)d_in[7];
    float* out = (float*)d_out;

    float *t1, *kv, *t2, *q, *att;
    cudaGetSymbolAddress((void**)&t1,  g_t1);
    cudaGetSymbolAddress((void**)&kv,  g_kv);
    cudaGetSymbolAddress((void**)&t2,  g_t2);
    cudaGetSymbolAddress((void**)&q,   g_q);
    cudaGetSymbolAddress((void**)&att, g_att);

    // kv-path 1x1 conv: [8,192,HW] -> [8,384,HW]
    conv1x1_kernel<<<dim3(HW / 128, C2 / 64, B), 128>>>(x, w_qkv, t1, C, C2);
    // q-path 1x1 conv: [8,192,HW] -> [8,192,HW]
    conv1x1_kernel<<<dim3(HW / 128, C / 64, B), 128>>>(y, w_query, t2, C, C);
    // depthwise 3x3 (SAME)
    dwconv3x3_kernel<<<dim3(H / 8, C2, B), 128>>>(t1, w_qkv_dw, kv, C2);
    dwconv3x3_kernel<<<dim3(H / 8, C, B), 128>>>(t2, w_query_dw, q, C);
    // split-K Gram of q,k + squared norms
    gram_kernel<<<dim3(NCHUNK, NH, B), 256>>>();
    // reduce + l2-normalize + temperature + softmax -> attn [32,48,48]
    reduce_softmax_kernel<<<B * NH, 256>>>(temperature);
    // attn @ v -> [8,192,HW]
    attnv_kernel<<<dim3(HW / 128, NH, B), 256>>>();
    // projection 1x1 conv -> d_out
    conv1x1_kernel<<<dim3(HW / 128, C / 64, B), 128>>>(att, w_proj, out, C, C);
}

// round 4
// speedup vs baseline: 1.3816x; 1.3816x over previous
#include <cuda_runtime.h>
#include <cuda_bf16.h>
#include <math.h>
#include <stdint.h>

// Problem constants (fixed shapes)
#define B    8
#define C    192
#define C2   384
#define NH   4
#define CH   48
#define H    128
#define WD   128
#define HW   16384
#define NCHUNK 16
#define CHUNK  1024

// ---------------- scratch (static __device__ arrays) ------------------------
__device__ float g_t1 [B * C2 * HW];
__device__ float g_kv [B * C2 * HW];
__device__ float g_t2 [B * C  * HW];
__device__ float g_q  [B * C  * HW];
__device__ float g_att[B * C  * HW];
__device__ float g_pS [B * NH * NCHUNK * CH * CH];
__device__ float g_pnq[B * NH * NCHUNK * CH];
__device__ float g_pnk[B * NH * NCHUNK * CH];
__device__ float g_attn[B * NH * CH * CH];
// transposed bf16 hi/lo activations: [B][HW][384] (hi 0:192, lo 192:384)
__device__ __nv_bfloat16 g_xt[(size_t)B * HW * 384];
// split weights: [Cout][384] bf16 (hi 0:192, lo 192:384)
__device__ __nv_bfloat16 g_w1[384 * 384];
__device__ __nv_bfloat16 g_w2[192 * 384];
__device__ __nv_bfloat16 g_w3[192 * 384];

// ---------------- PTX helpers (sm_103 baseline ISA only) --------------------
__device__ __forceinline__ uint32_t smem_u32(const void* p) {
    uint32_t a;
    asm("{ .reg .u64 t; cvta.to.shared.u64 t, %1; cvt.u32.u64 %0, t; }"
        : "=r"(a) : "l"(p));
    return a;
}
#define CP16(d, s) \
    asm volatile("cp.async.cg.shared.global [%0], [%1], 16;" :: "r"(d), "l"(s))
#define CP_COMMIT() asm volatile("cp.async.commit_group;")
#define CP_WAIT(n)  asm volatile("cp.async.wait_group %0;" :: "n"(n))

__device__ __forceinline__ void ldm4(uint32_t* r, uint32_t addr) {
    asm volatile("ldmatrix.sync.aligned.m8n8.x4.shared.b16 {%0,%1,%2,%3}, [%4];"
        : "=r"(r[0]), "=r"(r[1]), "=r"(r[2]), "=r"(r[3]) : "r"(addr));
}
__device__ __forceinline__ void mma_bf16(float* c, const uint32_t* a,
                                         const uint32_t* b) {
    asm volatile(
        "mma.sync.aligned.m16n8k16.row.col.f32.bf16.bf16.f32 "
        "{%0,%1,%2,%3}, {%4,%5,%6,%7}, {%8,%9}, {%0,%1,%2,%3};"
        : "+f"(c[0]), "+f"(c[1]), "+f"(c[2]), "+f"(c[3])
        : "r"(a[0]), "r"(a[1]), "r"(a[2]), "r"(a[3]), "r"(b[0]), "r"(b[1]));
}

// ---------------- weight split: W[Cout][192] -> [Cout][384] bf16 ------------
__global__ void prep_w_kernel(const float* __restrict__ w,
                              __nv_bfloat16* __restrict__ o) {
    int m = blockIdx.x;
    int k = threadIdx.x;
    float v = w[(size_t)m * 192 + k];
    __nv_bfloat16 hi = __float2bfloat16(v);
    __nv_bfloat16 lo = __float2bfloat16(v - __bfloat162float(hi));
    o[(size_t)m * 384 + k]       = hi;
    o[(size_t)m * 384 + 192 + k] = lo;
}

// ---------------- activation split+transpose: [B,192,HW] -> [B,HW,384] bf16 -
__global__ __launch_bounds__(256) void split_transpose_kernel(
    const float* __restrict__ in, __nv_bfloat16* __restrict__ out)
{
    const int n0 = blockIdx.x * 64;
    const int b  = blockIdx.y;
    __shared__ __nv_bfloat16 sT[64][390];

    const float* ip = in + (size_t)b * 192 * HW + n0;
    const int nn = threadIdx.x & 63;
    const int kq = threadIdx.x >> 6;

    for (int k0 = 0; k0 < 192; k0 += 8) {
        int k = k0 + kq * 2;
        float v0 = ip[(size_t)k * HW + nn];
        float v1 = ip[(size_t)(k + 1) * HW + nn];
        __nv_bfloat16 h0 = __float2bfloat16(v0);
        __nv_bfloat16 h1 = __float2bfloat16(v1);
        __nv_bfloat16 l0 = __float2bfloat16(v0 - __bfloat162float(h0));
        __nv_bfloat16 l1 = __float2bfloat16(v1 - __bfloat162float(h1));
        *(__nv_bfloat162*)(&sT[nn][k])       = __nv_bfloat162(h0, h1);
        *(__nv_bfloat162*)(&sT[nn][192 + k]) = __nv_bfloat162(l0, l1);
    }
    __syncthreads();

    // FIX (R4): row stride is 384 bf16 = 192 uint32 (was 96 -> scrambled output)
    uint32_t* op = (uint32_t*)(out + ((size_t)b * HW + n0) * 384);
    for (int idx = threadIdx.x; idx < 64 * 192; idx += 256) {
        int r = idx / 192, u = idx - r * 192;
        op[(size_t)r * 192 + u] = *(const uint32_t*)(&sT[r][u * 2]);
    }
}

// ---------------- HMMA GEMM: out[b,m,n] = sum_k W[m,k]*X[k,n] ----------------
// Block tile: 128 pixels (MMA-M) x 192 couts (MMA-N). Virtual K = 576
// (3 hi/lo terms x 192), 18 chunks of 32. 2-stage cp.async pipeline.
#define APITCH  80
#define A_STAGE (128 * APITCH)   // 10240
#define B_STAGE (192 * APITCH)   // 15360
#define SM_A    0
#define SM_B    (2 * A_STAGE)    // 20480
#define GSM_TOTAL (2 * A_STAGE + 2 * B_STAGE)  // 51200

__device__ __forceinline__ void g_load_chunk(
    uint32_t sb, const char* abase, const char* bbase, int tid, int c, int stage)
{
    const int term = c / 6;
    const int kk = (c - term * 6) * 32;
    const int aoff2 = ((term == 2 ? 192 : 0) + kk) * 2;  // bytes
    const int boff2 = ((term == 1 ? 192 : 0) + kk) * 2;
    const uint32_t sa  = sb + SM_A + stage * A_STAGE;
    const uint32_t sbm = sb + SM_B + stage * B_STAGE;
#pragma unroll
    for (int p = 0; p < 2; p++) {
        int idx = p * 256 + tid;
        int row = idx >> 2, q = idx & 3;
        CP16(sa + row * APITCH + q * 16,
             abase + (size_t)row * 768 + aoff2 + q * 16);
    }
#pragma unroll
    for (int p = 0; p < 3; p++) {
        int idx = p * 256 + tid;
        int row = idx >> 2, q = idx & 3;
        CP16(sbm + row * APITCH + q * 16,
             bbase + (size_t)row * 768 + boff2 + q * 16);
    }
    CP_COMMIT();
}

__global__ __launch_bounds__(256) void gemm_hmma_kernel(
    const __nv_bfloat16* __restrict__ xt, const __nv_bfloat16* __restrict__ wsp,
    float* __restrict__ out, int Cout)
{
    extern __shared__ char smem[];
    const uint32_t sb = smem_u32(smem);
    const int pix0  = blockIdx.x * 128;
    const int cout0 = blockIdx.y * 192;
    const int b     = blockIdx.z;
    const int tid   = threadIdx.x;
    const int lane  = tid & 31, wid = tid >> 5;
    const int wy = wid & 1;    // pixel half (64 each)
    const int wx = wid >> 1;   // cout quarter (48 each)

    const char* abase = (const char*)(xt + ((size_t)(b * HW) + pix0) * 384);
    const char* bbase = (const char*)(wsp + (size_t)cout0 * 384);

    float acc[4][6][4];
#pragma unroll
    for (int i = 0; i < 4; i++)
#pragma unroll
        for (int j = 0; j < 6; j++)
#pragma unroll
            for (int t = 0; t < 4; t++) acc[i][j][t] = 0.0f;

    g_load_chunk(sb, abase, bbase, tid, 0, 0);

    for (int c = 0; c < 18; c++) {
        if (c + 1 < 18) {
            g_load_chunk(sb, abase, bbase, tid, c + 1, (c + 1) & 1);
            CP_WAIT(1);
        } else {
            CP_WAIT(0);
        }
        __syncthreads();

        const uint32_t sa  = sb + SM_A + (c & 1) * A_STAGE;
        const uint32_t sbm = sb + SM_B + (c & 1) * B_STAGE;
#pragma unroll
        for (int ks = 0; ks < 2; ks++) {
            uint32_t afr[4][4];
#pragma unroll
            for (int mi = 0; mi < 4; mi++)
                ldm4(afr[mi], sa + (wy * 64 + mi * 16 + (lane & 15)) * APITCH
                              + ks * 32 + (lane >> 4) * 16);
            uint32_t bfr[3][4];
#pragma unroll
            for (int nj = 0; nj < 3; nj++)
                ldm4(bfr[nj], sbm + (wx * 48 + nj * 16 + (lane & 7)
                                     + (lane >> 4) * 8) * APITCH
                              + ks * 32 + ((lane >> 3) & 1) * 16);
#pragma unroll
            for (int mi = 0; mi < 4; mi++)
#pragma unroll
                for (int nj = 0; nj < 3; nj++) {
                    mma_bf16(acc[mi][nj * 2],     afr[mi], &bfr[nj][0]);
                    mma_bf16(acc[mi][nj * 2 + 1], afr[mi], &bfr[nj][2]);
                }
        }
        // FIX (R4): barrier before next iteration's cp.async overwrites the
        // stage this iteration just read (2-stage ring reuses it at c+2).
        __syncthreads();
    }

    // epilogue: D[row=pixel][col=cout] fragment -> channel-major out
    const int prow = lane >> 2;
    const int ccol = (lane & 3) * 2;
#pragma unroll
    for (int mi = 0; mi < 4; mi++) {
        const int p = pix0 + wy * 64 + mi * 16 + prow;
#pragma unroll
        for (int ni = 0; ni < 6; ni++) {
            const int co = cout0 + wx * 48 + ni * 8 + ccol;
            float* o0 = out + ((size_t)b * Cout + co) * HW + p;
            o0[0]      = acc[mi][ni][0];
            o0[HW]     = acc[mi][ni][1];
            o0[8]      = acc[mi][ni][2];
            o0[HW + 8] = acc[mi][ni][3];
        }
    }
}

// ---------------- depthwise 3x3, SAME padding --------------------------------
__global__ __launch_bounds__(128) void dwconv3x3_kernel(
    const float* __restrict__ in, const float* __restrict__ w9,
    float* __restrict__ out, int Cc)
{
    const int y0 = blockIdx.x * 8;
    const int c  = blockIdx.y;
    const int b  = blockIdx.z;
    const int x  = threadIdx.x;

    __shared__ float s[10][130];
    const float* ip = in  + ((size_t)b * Cc + c) * HW;
    float*       op = out + ((size_t)b * Cc + c) * HW;

    float wr[9];
#pragma unroll
    for (int t = 0; t < 9; t++) wr[t] = w9[c * 9 + t];

#pragma unroll
    for (int r = 0; r < 10; r++) {
        int yy = y0 - 1 + r;
        s[r][x + 1] = (yy >= 0 && yy < H) ? ip[yy * WD + x] : 0.0f;
    }
    if (x == 0) {
#pragma unroll
        for (int r = 0; r < 10; r++) { s[r][0] = 0.0f; s[r][129] = 0.0f; }
    }
    __syncthreads();

#pragma unroll
    for (int ry = 0; ry < 8; ry++) {
        float a =
            s[ry + 0][x + 0] * wr[0] + s[ry + 0][x + 1] * wr[1] + s[ry + 0][x + 2] * wr[2] +
            s[ry + 1][x + 0] * wr[3] + s[ry + 1][x + 1] * wr[4] + s[ry + 1][x + 2] * wr[5] +
            s[ry + 2][x + 0] * wr[6] + s[ry + 2][x + 1] * wr[7] + s[ry + 2][x + 2] * wr[8];
        op[(y0 + ry) * WD + x] = a;
    }
}

// ---------------- split-K Gram + norms ---------------------------------------
__global__ __launch_bounds__(256) void gram_kernel()
{
    const int ck = blockIdx.x, h = blockIdx.y, b = blockIdx.z;
    const int tid = threadIdx.x;
    const int tx = tid & 15, ty = tid >> 4;

    const float* qp = g_q  + ((size_t)b * C  + h * CH) * HW + ck * CHUNK;
    const float* kp = g_kv + ((size_t)b * C2 + h * CH) * HW + ck * CHUNK;

    __shared__ float sQ[32][49];
    __shared__ float sK[32][49];

    float acc[3][3];
#pragma unroll
    for (int i = 0; i < 3; i++)
#pragma unroll
        for (int j = 0; j < 3; j++) acc[i][j] = 0.0f;
    float sq[3] = {0.f, 0.f, 0.f}, sk2[3] = {0.f, 0.f, 0.f};

    for (int nb = 0; nb < CHUNK; nb += 32) {
#pragma unroll
        for (int e = 0; e < 6; e++) {
            int idx = tid + e * 256;
            int cc = idx >> 5, nn = idx & 31;
            sQ[nn][cc] = qp[(size_t)cc * HW + nb + nn];
            sK[nn][cc] = kp[(size_t)cc * HW + nb + nn];
        }
        __syncthreads();
#pragma unroll
        for (int kk = 0; kk < 32; kk++) {
            float a0 = sQ[kk][ty * 3 + 0];
            float a1 = sQ[kk][ty * 3 + 1];
            float a2 = sQ[kk][ty * 3 + 2];
            float b0 = sK[kk][tx * 3 + 0];
            float b1 = sK[kk][tx * 3 + 1];
            float b2 = sK[kk][tx * 3 + 2];
            acc[0][0] += a0 * b0; acc[0][1] += a0 * b1; acc[0][2] += a0 * b2;
            acc[1][0] += a1 * b0; acc[1][1] += a1 * b1; acc[1][2] += a1 * b2;
            acc[2][0] += a2 * b0; acc[2][1] += a2 * b1; acc[2][2] += a2 * b2;
            if (tx == 0) { sq[0]  += a0 * a0; sq[1]  += a1 * a1; sq[2]  += a2 * a2; }
            if (ty == 0) { sk2[0] += b0 * b0; sk2[1] += b1 * b1; sk2[2] += b2 * b2; }
        }
        __syncthreads();
    }

    const int base = (b * NH + h) * NCHUNK + ck;
    float* ps = g_pS + (size_t)base * (CH * CH);
#pragma unroll
    for (int i = 0; i < 3; i++)
#pragma unroll
        for (int j = 0; j < 3; j++)
            ps[(ty * 3 + i) * CH + tx * 3 + j] = acc[i][j];
    if (tx == 0) {
#pragma unroll
        for (int i = 0; i < 3; i++) g_pnq[base * CH + ty * 3 + i] = sq[i];
    }
    if (ty == 0) {
#pragma unroll
        for (int j = 0; j < 3; j++) g_pnk[base * CH + tx * 3 + j] = sk2[j];
    }
}

// ---------------- reduce, normalize, temperature, softmax --------------------
__global__ __launch_bounds__(256) void reduce_softmax_kernel(
    const float* __restrict__ temperature)
{
    const int bh = blockIdx.x;
    const int h  = bh & (NH - 1);
    const int tid = threadIdx.x;

    __shared__ float sS[CH * CH];
    __shared__ float snq[CH], snk[CH];

    for (int idx = tid; idx < CH * CH; idx += 256) {
        float s = 0.0f;
        for (int ck = 0; ck < NCHUNK; ck++)
            s += g_pS[(size_t)(bh * NCHUNK + ck) * (CH * CH) + idx];
        sS[idx] = s;
    }
    if (tid < CH) {
        float s = 0.0f;
        for (int ck = 0; ck < NCHUNK; ck++)
            s += g_pnq[(bh * NCHUNK + ck) * CH + tid];
        snq[tid] = fmaxf(sqrtf(s), 1e-12f);
    } else if (tid >= 64 && tid < 64 + CH) {
        int d = tid - 64;
        float s = 0.0f;
        for (int ck = 0; ck < NCHUNK; ck++)
            s += g_pnk[(bh * NCHUNK + ck) * CH + d];
        snk[d] = fmaxf(sqrtf(s), 1e-12f);
    }
    __syncthreads();

    const float t = temperature[h];
    for (int idx = tid; idx < CH * CH; idx += 256) {
        int cc = idx / CH, d = idx - cc * CH;
        sS[idx] = sS[idx] * t / (snq[cc] * snk[d]);
    }
    __syncthreads();

    if (tid < CH) {
        const int cc = tid;
        float m = -1e30f;
        for (int d = 0; d < CH; d++) m = fmaxf(m, sS[cc * CH + d]);
        float sum = 0.0f;
        for (int d = 0; d < CH; d++) {
            float e = expf(sS[cc * CH + d] - m);
            sS[cc * CH + d] = e;
            sum += e;
        }
        float inv = 1.0f / sum;
        for (int d = 0; d < CH; d++)
            g_attn[(size_t)bh * (CH * CH) + cc * CH + d] = sS[cc * CH + d] * inv;
    }
}

// ---------------- out[c,n] = sum_d attn[c,d] * v[d,n] ------------------------
__global__ __launch_bounds__(256) void attnv_kernel()
{
    const int n0 = blockIdx.x * 128;
    const int h  = blockIdx.y, b = blockIdx.z;
    const int tid = threadIdx.x;
    const int tx = tid & 31, ty = tid >> 5;

    __shared__ float sA[CH][CH];
    __shared__ __align__(16) float sV[CH][128];

    const float* vp = g_kv + ((size_t)b * C2 + C + h * CH) * HW + n0;
    const float* ap = g_attn + (size_t)(b * NH + h) * (CH * CH);

    for (int idx = tid; idx < CH * CH; idx += 256)
        sA[idx / CH][idx % CH] = ap[idx];
#pragma unroll
    for (int e = 0; e < 6; e++) {
        int idx = tid + e * 256;
        int d = idx >> 5, nv = idx & 31;
        ((float4*)(&sV[d][0]))[nv] = ((const float4*)(vp + (size_t)d * HW))[nv];
    }
    __syncthreads();

    float4 acc[6];
#pragma unroll
    for (int i = 0; i < 6; i++) acc[i] = make_float4(0.f, 0.f, 0.f, 0.f);

    for (int d = 0; d < CH; d++) {
        float4 vv = ((const float4*)(&sV[d][0]))[tx];
#pragma unroll
        for (int i = 0; i < 6; i++) {
            float a = sA[ty * 6 + i][d];
            acc[i].x += a * vv.x; acc[i].y += a * vv.y;
            acc[i].z += a * vv.z; acc[i].w += a * vv.w;
        }
    }

    float* op = g_att + ((size_t)b * C + h * CH + ty * 6) * HW + n0 + tx * 4;
#pragma unroll
    for (int i = 0; i < 6; i++)
        *((float4*)(op + (size_t)i * HW)) = acc[i];
}

// ---------------- launcher ----------------------------------------------------
extern "C" void kernel_launch(void* const* d_in, const int* in_sizes, int n_in,
                              void* d_out, int out_size)
{
    const float* x           = (const float*)d_in[0];
    const float* y           = (const float*)d_in[1];
    const float* w_qkv       = (const float*)d_in[2];
    const float* w_qkv_dw    = (const float*)d_in[3];
    const float* w_query     = (const float*)d_in[4];
    const float* w_query_dw  = (const float*)d_in[5];
    const float* w_proj      = (const float*)d_in[6];
    const float* temperature = (const float*)d_in[7];
    float* out = (float*)d_out;

    float *t1, *kv, *t2, *q, *att;
    __nv_bfloat16 *xt, *w1, *w2, *w3;
    cudaGetSymbolAddress((void**)&t1,  g_t1);
    cudaGetSymbolAddress((void**)&kv,  g_kv);
    cudaGetSymbolAddress((void**)&t2,  g_t2);
    cudaGetSymbolAddress((void**)&q,   g_q);
    cudaGetSymbolAddress((void**)&att, g_att);
    cudaGetSymbolAddress((void**)&xt,  g_xt);
    cudaGetSymbolAddress((void**)&w1,  g_w1);
    cudaGetSymbolAddress((void**)&w2,  g_w2);
    cudaGetSymbolAddress((void**)&w3,  g_w3);

    static int smem_set = 0;
    if (!smem_set) {
        cudaFuncSetAttribute(gemm_hmma_kernel,
                             cudaFuncAttributeMaxDynamicSharedMemorySize, GSM_TOTAL);
        smem_set = 1;
    }

    // weight hi/lo split (tiny)
    prep_w_kernel<<<384, 192>>>(w_qkv,   w1);
    prep_w_kernel<<<192, 192>>>(w_query, w2);
    prep_w_kernel<<<192, 192>>>(w_proj,  w3);

    // conv1: x -> t1 [8,384,HW]
    split_transpose_kernel<<<dim3(HW / 64, B), 256>>>(x, xt);
    gemm_hmma_kernel<<<dim3(HW / 128, 2, B), 256, GSM_TOTAL>>>(xt, w1, t1, 384);

    // conv2: y -> t2 [8,192,HW]
    split_transpose_kernel<<<dim3(HW / 64, B), 256>>>(y, xt);
    gemm_hmma_kernel<<<dim3(HW / 128, 1, B), 256, GSM_TOTAL>>>(xt, w2, t2, 192);

    // depthwise 3x3
    dwconv3x3_kernel<<<dim3(H / 8, C2, B), 128>>>(t1, w_qkv_dw, kv, C2);
    dwconv3x3_kernel<<<dim3(H / 8, C, B), 128>>>(t2, w_query_dw, q, C);

    // attention
    gram_kernel<<<dim3(NCHUNK, NH, B), 256>>>();
    reduce_softmax_kernel<<<B * NH, 256>>>(temperature);
    attnv_kernel<<<dim3(HW / 128, NH, B), 256>>>();

    // conv3: att -> out
    split_transpose_kernel<<<dim3(HW / 64, B), 256>>>(att, xt);
    gemm_hmma_kernel<<<dim3(HW / 128, 1, B), 256, GSM_TOTAL>>>(xt, w3, out, 192);
}